// round 16
// baseline (speedup 1.0000x reference)
#include <cuda_runtime.h>
#include <math.h>

#define Nn   12288
#define Ee   393216
#define Bb   16
#define FIN  15
#define Hh   32
#define H2   64
#define NC   11

// ---------------- scratch (static device globals; no allocs) ----------------
// invariant: g_cd, g_sum, g_sq, g_emb are ZERO at kernel_launch entry
// (zero-initialized at load; re-zeroed by k_mlp3 tail blocks each run).
__device__ unsigned long long g_cd[Nn];   // [cnt:24 | deg fixed-point 2^-24 : 40]
__device__ float          g_ew[Ee];
__device__ unsigned short g_slot[Ee];
__device__ int            g_rowptr[Nn + 1];
__device__ float          g_dis[Nn];
__device__ float2         g_pack[Ee];     // (col bits, val = ew * dis[col])

__device__ float g_x16[Nn * 16];
__device__ float g_z1[Nn * Hh];
__device__ float g_z2[Nn * H2];
__device__ float g_z3[Nn * H2];

__device__ float g_sum[3 * 64];
__device__ float g_sq [3 * 64];

__device__ float g_emb[Bb * 64];
__device__ float g_fc1[Bb * 512];
__device__ float g_fc2[Bb * 256];

#define FIX_SCALE 16777216.0f
#define FIX_MASK  ((1ull << 40) - 1ull)

// ---------------- edge weights + degree/count (one 64b atomic) + x pad ------
__global__ void k_edge(const float* __restrict__ ea, const float* __restrict__ we,
                       const float* __restrict__ be, const int* __restrict__ ei,
                       const float* __restrict__ x) {
    int e = blockIdx.x * blockDim.x + threadIdx.x;
    if (e < Nn * 16) {             // fold x padding (15 -> 16) into this launch
        int f = e & 15;
        g_x16[e] = (f < FIN) ? x[(e >> 4) * FIN + f] : 0.f;
    }
    if (e >= Ee) return;
    float2 a = ((const float2*)ea)[e];
    float t = a.x * we[0] + a.y * we[1] + be[0];
    float w = 1.f / (1.f + __expf(-t));
    g_ew[e] = w;
    int r = ei[e];
    unsigned long long add = (1ull << 40) | (unsigned long long)(w * FIX_SCALE);
    unsigned long long old = atomicAdd(&g_cd[r], add);
    g_slot[e] = (unsigned short)(old >> 40);   // prior count = this edge's slot
}

// ---- single-block scan of counts -> rowptr; also decode deg -> dis ---------
__global__ void k_scan() {
    __shared__ int warpsum[32];
    __shared__ int warpoff[32];
    int t = threadIdx.x;            // 1024 threads
    const int C = Nn / 1024;        // 12
    int base = t * C;
    int pre[C];
    int s = 0;
    #pragma unroll
    for (int c = 0; c < C; c++) {
        unsigned long long cd = g_cd[base + c];
        int cnt = (int)(cd >> 40);
        float deg = (float)(cd & FIX_MASK) * (1.f / FIX_SCALE);
        g_dis[base + c] = rsqrtf(1.f + deg);
        pre[c] = s; s += cnt;
    }
    int lane = t & 31, wid = t >> 5;
    int v = s;
    #pragma unroll
    for (int o = 1; o < 32; o <<= 1) {
        int n = __shfl_up_sync(0xffffffffu, v, o);
        if (lane >= o) v += n;
    }
    if (lane == 31) warpsum[wid] = v;
    __syncthreads();
    if (wid == 0) {
        int ws = warpsum[lane];
        #pragma unroll
        for (int o = 1; o < 32; o <<= 1) {
            int n = __shfl_up_sync(0xffffffffu, ws, o);
            if (lane >= o) ws += n;
        }
        warpoff[lane] = ws;
    }
    __syncthreads();
    int incl = v + (wid > 0 ? warpoff[wid - 1] : 0);
    int off = incl - s;
    #pragma unroll
    for (int c = 0; c < C; c++) g_rowptr[base + c] = off + pre[c];
    if (t == 1023) g_rowptr[Nn] = incl;
}

// ---------------- scatter: NO atomics (slot precomputed) --------------------
__global__ void k_scatter(const int* __restrict__ ei) {
    int e = blockIdx.x * blockDim.x + threadIdx.x;
    if (e >= Ee) return;
    int r = ei[e];
    int c = ei[Ee + e];
    int p = g_rowptr[r] + (int)g_slot[e];
    float val = g_ew[e] * g_dis[c];
    g_pack[p] = make_float2(__int_as_float(c), val);
}

// ---- fused GCN layer: SpMM -> GEMM -> BN stats -----------------------------
// Warp u owns rows 2u, 2u+1. Lane-groups of LPE lanes stream row A's edges
// then row B's edges (single accumulator per stream, x4 unrolled, no shuffles
// in the hot loop). sW loads overlap edge streaming (barrier deferred).
// Self-loop contributes d*v at init; final *= d gives the required d^2 * x_i.
#define ACC4(p, v) do { \
    acc.x = fmaf((p).y, (v).x, acc.x); \
    acc.y = fmaf((p).y, (v).y, acc.y); \
    acc.z = fmaf((p).y, (v).z, acc.z); \
    acc.w = fmaf((p).y, (v).w, acc.w); } while (0)

template <int FI, int FIeff, int FO>
__global__ void __launch_bounds__(128) k_layer(
    const float* __restrict__ in,        // [N,FI] already BN+ReLU'd (or x16)
    const float* __restrict__ W,         // [FIeff,FO]
    const float* __restrict__ bias,
    float* __restrict__ out,             // [N,FO] raw
    float* __restrict__ sum_out, float* __restrict__ sq_out)
{
    constexpr int LPE = FI / 4;
    constexpr int EPW = 32 / LPE;        // 2 (FI=64), 4 (FI=32), 8 (FI=16)
    __shared__ float  sW[FIeff * FO];
    __shared__ float4 sRow[4][2][16];    // [warp][row A/B][feature quad]
    __shared__ float  sSum[FO], sSq[FO];
    int tid = threadIdx.x;
    for (int i = tid; i < FIeff * FO; i += 128) sW[i] = W[i];
    if (tid < FO) { sSum[tid] = 0.f; sSq[tid] = 0.f; }
    // NO barrier yet: sW not needed until after the edge streams.

    int warp = tid >> 5, lane = tid & 31;
    int eh = lane / LPE;        // edge-group id
    int fl = lane % LPE;        // feature quad
    float b0 = (lane < FO) ? bias[lane] : 0.f;
    float b1 = (FO > 32) ? bias[lane + 32] : 0.f;

    const float4* in4 = (const float4*)in;
    int u  = blockIdx.x * 4 + warp;      // 1536 blocks * 4 warps = 6144
    int rA = 2 * u, rB = rA + 1;
    float dA = g_dis[rA], dB = g_dis[rB];
    int sA = g_rowptr[rA], eA = g_rowptr[rA + 1], eB = g_rowptr[rA + 2];

    float4 accA, accB;
    {   // ---- stream row A ----
        float4 acc = make_float4(0.f, 0.f, 0.f, 0.f);
        if (eh == 0) {   // self-loop (weight 1): contributes dA * v here
            float4 v = __ldg(&in4[rA * LPE + fl]);
            acc.x = dA * v.x; acc.y = dA * v.y; acc.z = dA * v.z; acc.w = dA * v.w;
        }
        int k = sA + eh;
        for (; k + 3 * EPW < eA; k += 4 * EPW) {
            float2 p0 = __ldg(&g_pack[k]);
            float2 p1 = __ldg(&g_pack[k + EPW]);
            float2 p2 = __ldg(&g_pack[k + 2 * EPW]);
            float2 p3 = __ldg(&g_pack[k + 3 * EPW]);
            float4 v0 = __ldg(&in4[__float_as_int(p0.x) * LPE + fl]);
            float4 v1 = __ldg(&in4[__float_as_int(p1.x) * LPE + fl]);
            float4 v2 = __ldg(&in4[__float_as_int(p2.x) * LPE + fl]);
            float4 v3 = __ldg(&in4[__float_as_int(p3.x) * LPE + fl]);
            ACC4(p0, v0); ACC4(p1, v1); ACC4(p2, v2); ACC4(p3, v3);
        }
        for (; k < eA; k += EPW) {
            float2 p0 = __ldg(&g_pack[k]);
            float4 v0 = __ldg(&in4[__float_as_int(p0.x) * LPE + fl]);
            ACC4(p0, v0);
        }
        accA = acc;
    }
    {   // ---- stream row B ----
        float4 acc = make_float4(0.f, 0.f, 0.f, 0.f);
        if (eh == 0) {
            float4 v = __ldg(&in4[rB * LPE + fl]);
            acc.x = dB * v.x; acc.y = dB * v.y; acc.z = dB * v.z; acc.w = dB * v.w;
        }
        int k = eA + eh;
        for (; k + 3 * EPW < eB; k += 4 * EPW) {
            float2 p0 = __ldg(&g_pack[k]);
            float2 p1 = __ldg(&g_pack[k + EPW]);
            float2 p2 = __ldg(&g_pack[k + 2 * EPW]);
            float2 p3 = __ldg(&g_pack[k + 3 * EPW]);
            float4 v0 = __ldg(&in4[__float_as_int(p0.x) * LPE + fl]);
            float4 v1 = __ldg(&in4[__float_as_int(p1.x) * LPE + fl]);
            float4 v2 = __ldg(&in4[__float_as_int(p2.x) * LPE + fl]);
            float4 v3 = __ldg(&in4[__float_as_int(p3.x) * LPE + fl]);
            ACC4(p0, v0); ACC4(p1, v1); ACC4(p2, v2); ACC4(p3, v3);
        }
        for (; k < eB; k += EPW) {
            float2 p0 = __ldg(&g_pack[k]);
            float4 v0 = __ldg(&in4[__float_as_int(p0.x) * LPE + fl]);
            ACC4(p0, v0);
        }
        accB = acc;
    }
    __syncwarp();
    // reduce over edge groups (both rows in one butterfly)
    #pragma unroll
    for (int o = LPE; o < 32; o <<= 1) {
        accA.x += __shfl_xor_sync(0xffffffffu, accA.x, o);
        accA.y += __shfl_xor_sync(0xffffffffu, accA.y, o);
        accA.z += __shfl_xor_sync(0xffffffffu, accA.z, o);
        accA.w += __shfl_xor_sync(0xffffffffu, accA.w, o);
        accB.x += __shfl_xor_sync(0xffffffffu, accB.x, o);
        accB.y += __shfl_xor_sync(0xffffffffu, accB.y, o);
        accB.z += __shfl_xor_sync(0xffffffffu, accB.z, o);
        accB.w += __shfl_xor_sync(0xffffffffu, accB.w, o);
    }
    accA.x *= dA; accA.y *= dA; accA.z *= dA; accA.w *= dA;
    accB.x *= dB; accB.y *= dB; accB.z *= dB; accB.w *= dB;
    if (eh == 0) sRow[warp][0][fl] = accA;
    if (eh == 1) sRow[warp][1][fl] = accB;
    __syncthreads();           // covers sRow, sW, sSum init

    // GEMM for both rows; W-column loads shared
    const float* hA = (const float*)&sRow[warp][0][0];
    const float* hB = (const float*)&sRow[warp][1][0];
    float oA0 = b0, oA1 = b1, oB0 = b0, oB1 = b1;
    #pragma unroll
    for (int f = 0; f < FIeff; f++) {
        float ha = hA[f], hb = hB[f];
        float wv0 = sW[f * FO + lane];
        oA0 = fmaf(ha, wv0, oA0);
        oB0 = fmaf(hb, wv0, oB0);
        if (FO > 32) {
            float wv1 = sW[f * FO + lane + 32];
            oA1 = fmaf(ha, wv1, oA1);
            oB1 = fmaf(hb, wv1, oB1);
        }
    }
    if (lane < FO) {
        out[rA * FO + lane] = oA0;
        out[rB * FO + lane] = oB0;
        atomicAdd(&sSum[lane], oA0 + oB0);
        atomicAdd(&sSq[lane],  oA0 * oA0 + oB0 * oB0);
    }
    if (FO > 32) {
        out[rA * FO + lane + 32] = oA1;
        out[rB * FO + lane + 32] = oB1;
        atomicAdd(&sSum[lane + 32], oA1 + oB1);
        atomicAdd(&sSq[lane + 32],  oA1 * oA1 + oB1 * oB1);
    }
    __syncthreads();
    if (tid < FO) {
        atomicAdd(&sum_out[tid], sSum[tid]);
        atomicAdd(&sq_out[tid],  sSq[tid]);
    }
}

// ---------------- in-place BN + ReLU (vectorized) ---------------------------
template <int F>
__global__ void __launch_bounds__(256) k_norm(
    float* __restrict__ z,
    const float* __restrict__ gam, const float* __restrict__ bet,
    const float* __restrict__ sum, const float* __restrict__ sq) {
    __shared__ float scl[F], shf[F];
    int t = threadIdx.x;
    if (t < F) {
        float mu  = sum[t] * (1.f / (float)Nn);
        float var = sq[t]  * (1.f / (float)Nn) - mu * mu;
        float inv = rsqrtf(var + 1e-5f);
        float sc  = gam[t] * inv;
        scl[t] = sc; shf[t] = bet[t] - sc * mu;
    }
    __syncthreads();
    int idx = blockIdx.x * 256 + t;          // float4 index; grid sized exactly
    float4 v = ((float4*)z)[idx];
    int f = (idx * 4) & (F - 1);             // F is a power of two
    v.x = fmaxf(fmaf(scl[f],     v.x, shf[f]),     0.f);
    v.y = fmaxf(fmaf(scl[f + 1], v.y, shf[f + 1]), 0.f);
    v.z = fmaxf(fmaf(scl[f + 2], v.z, shf[f + 2]), 0.f);
    v.w = fmaxf(fmaf(scl[f + 3], v.w, shf[f + 3]), 0.f);
    ((float4*)z)[idx] = v;
}

// ---------------- max pool: sorted-batch segment flush (BN3 inline) ---------
__global__ void __launch_bounds__(256) k_pool(
    const float* __restrict__ z3, const int* __restrict__ batch,
    const float* __restrict__ gam, const float* __restrict__ bet) {
    __shared__ float scl[64], shf[64];
    int t = threadIdx.x;
    if (t < 64) {
        float mu  = g_sum[128 + t] * (1.f / (float)Nn);
        float var = g_sq [128 + t] * (1.f / (float)Nn) - mu * mu;
        float inv = rsqrtf(var + 1e-5f);
        float sc  = gam[t] * inv;
        scl[t] = sc; shf[t] = bet[t] - sc * mu;
    }
    __syncthreads();
    int f  = t & 63;
    int r0 = blockIdx.x * 128 + (t >> 6);
    float sc = scl[f], sh = shf[f];
    int curb = -1; float cm = 0.f;
    for (int r = r0; r < blockIdx.x * 128 + 128; r += 4) {
        int b = batch[r];
        float v = fmaxf(fmaf(sc, z3[r * 64 + f], sh), 0.f);
        if (b != curb) {
            if (curb >= 0) atomicMax((int*)&g_emb[curb * 64 + f], __float_as_int(cm));
            curb = b; cm = v;
        } else cm = fmaxf(cm, v);
    }
    if (curb >= 0) atomicMax((int*)&g_emb[curb * 64 + f], __float_as_int(cm));
}

// ---------------- MLP head --------------------------------------------------
__global__ void __launch_bounds__(256) k_mlp1(
    const float* __restrict__ wf1, const float* __restrict__ bf1,
    const float* __restrict__ gf1, const float* __restrict__ bef1,
    float* __restrict__ out) {
    __shared__ float se[16 * 64];
    __shared__ float sz[16][64];
    __shared__ float scl[64], shf[64];
    int t = threadIdx.x;
    for (int i = t; i < 1024; i += 256) se[i] = g_emb[i];
    __syncthreads();
    int cl = t & 63;
    int r0 = t >> 6;
    int c = blockIdx.x * 64 + cl;
    #pragma unroll
    for (int q = 0; q < 4; q++) {
        int r = r0 + q * 4;
        float a0 = 0.f, a1 = 0.f, a2 = 0.f, a3 = 0.f;
        #pragma unroll
        for (int k = 0; k < 64; k += 4) {
            a0 += se[r * 64 + k]     * wf1[(k)     * 512 + c];
            a1 += se[r * 64 + k + 1] * wf1[(k + 1) * 512 + c];
            a2 += se[r * 64 + k + 2] * wf1[(k + 2) * 512 + c];
            a3 += se[r * 64 + k + 3] * wf1[(k + 3) * 512 + c];
        }
        sz[r][cl] = bf1[c] + ((a0 + a1) + (a2 + a3));
    }
    __syncthreads();
    if (t < 64) {
        float s = 0.f, q = 0.f;
        for (int r = 0; r < 16; r++) { float v = sz[r][t]; s += v; q += v * v; }
        float mu = s * (1.f / Bb), var = q * (1.f / Bb) - mu * mu;
        float inv = rsqrtf(var + 1e-5f);
        float sc = gf1[blockIdx.x * 64 + t] * inv;
        scl[t] = sc; shf[t] = bef1[blockIdx.x * 64 + t] - sc * mu;
    }
    __syncthreads();
    #pragma unroll
    for (int q = 0; q < 4; q++) {
        int r = r0 + q * 4;
        g_fc1[r * 512 + c] = fmaxf(scl[cl] * sz[r][cl] + shf[cl], 0.f);
    }
    if (blockIdx.x == 0)
        for (int i = t; i < 1024; i += 256) out[Bb * NC + i] = se[i];
}

__global__ void __launch_bounds__(256) k_mlp2(
    const float* __restrict__ wf2, const float* __restrict__ bf2,
    const float* __restrict__ gf2, const float* __restrict__ bef2) {
    __shared__ float sf[16 * 512];
    __shared__ float sz[16][32];
    __shared__ float scl[32], shf[32];
    int t = threadIdx.x;
    for (int i = t; i < 8192; i += 256) sf[i] = g_fc1[i];
    __syncthreads();
    int cl = t & 31;
    int r0 = t >> 5;
    int c = blockIdx.x * 32 + cl;
    #pragma unroll
    for (int q = 0; q < 2; q++) {
        int r = r0 + q * 8;
        float a0 = 0.f, a1 = 0.f, a2 = 0.f, a3 = 0.f;
        for (int k = 0; k < 512; k += 4) {
            a0 += sf[r * 512 + k]     * wf2[(k)     * 256 + c];
            a1 += sf[r * 512 + k + 1] * wf2[(k + 1) * 256 + c];
            a2 += sf[r * 512 + k + 2] * wf2[(k + 2) * 256 + c];
            a3 += sf[r * 512 + k + 3] * wf2[(k + 3) * 256 + c];
        }
        sz[r][cl] = bf2[c] + ((a0 + a1) + (a2 + a3));
    }
    __syncthreads();
    if (t < 32) {
        float s = 0.f, q = 0.f;
        for (int r = 0; r < 16; r++) { float v = sz[r][t]; s += v; q += v * v; }
        float mu = s * (1.f / Bb), var = q * (1.f / Bb) - mu * mu;
        float inv = rsqrtf(var + 1e-5f);
        float sc = gf2[blockIdx.x * 32 + t] * inv;
        scl[t] = sc; shf[t] = bef2[blockIdx.x * 32 + t] - sc * mu;
    }
    __syncthreads();
    #pragma unroll
    for (int q = 0; q < 2; q++) {
        int r = r0 + q * 8;
        g_fc2[r * 256 + c] = fmaxf(scl[cl] * sz[r][cl] + shf[cl], 0.f);
    }
}

// block 0: fc3 + log_softmax.  blocks 1..4: zero counters for next run.
__global__ void __launch_bounds__(256) k_mlp3(
    const float* __restrict__ wf3, const float* __restrict__ bf3,
    float* __restrict__ out) {
    int t = threadIdx.x;
    if (blockIdx.x > 0) {
        int g = (blockIdx.x - 1) * 256 + t;        // 1024 threads
        for (int i = g; i < Nn; i += 1024) g_cd[i] = 0ull;
        if (g < 192) { g_sum[g] = 0.f; g_sq[g] = 0.f; }
        g_emb[g] = 0.f;                            // 1024 elements exactly
        return;
    }
    __shared__ float sf[16 * 256];
    __shared__ float sl[16][11];
    for (int i = t; i < 4096; i += 256) sf[i] = g_fc2[i];
    __syncthreads();
    if (t < Bb * NC) {
        int r = t / NC, j = t % NC;
        float a0 = 0.f, a1 = 0.f, a2 = 0.f, a3 = 0.f;
        for (int k = 0; k < 256; k += 4) {
            a0 += sf[r * 256 + k]     * wf3[(k)     * NC + j];
            a1 += sf[r * 256 + k + 1] * wf3[(k + 1) * NC + j];
            a2 += sf[r * 256 + k + 2] * wf3[(k + 2) * NC + j];
            a3 += sf[r * 256 + k + 3] * wf3[(k + 3) * NC + j];
        }
        sl[r][j] = bf3[j] + ((a0 + a1) + (a2 + a3));
    }
    __syncthreads();
    if (t < Bb) {
        float m = -1e30f;
        for (int j = 0; j < NC; j++) m = fmaxf(m, sl[t][j]);
        float s = 0.f;
        for (int j = 0; j < NC; j++) s += expf(sl[t][j] - m);
        float l = m + logf(s);
        for (int j = 0; j < NC; j++) out[t * NC + j] = sl[t][j] - l;
    }
}

// ---------------- launcher ----------------
extern "C" void kernel_launch(void* const* d_in, const int* in_sizes, int n_in,
                              void* d_out, int out_size) {
    const float* x      = (const float*)d_in[0];
    const float* ea     = (const float*)d_in[1];
    const float* w_edge = (const float*)d_in[2];
    const float* b_edge = (const float*)d_in[3];
    const float* w1  = (const float*)d_in[4];  const float* b1  = (const float*)d_in[5];
    const float* g1  = (const float*)d_in[6];  const float* be1 = (const float*)d_in[7];
    const float* w2  = (const float*)d_in[8];  const float* b2  = (const float*)d_in[9];
    const float* g2  = (const float*)d_in[10]; const float* be2 = (const float*)d_in[11];
    const float* w3  = (const float*)d_in[12]; const float* b3  = (const float*)d_in[13];
    const float* g3  = (const float*)d_in[14]; const float* be3 = (const float*)d_in[15];
    const float* wf1 = (const float*)d_in[16]; const float* bf1 = (const float*)d_in[17];
    const float* gf1 = (const float*)d_in[18]; const float* bef1= (const float*)d_in[19];
    const float* wf2 = (const float*)d_in[20]; const float* bf2 = (const float*)d_in[21];
    const float* gf2 = (const float*)d_in[22]; const float* bef2= (const float*)d_in[23];
    const float* wf3 = (const float*)d_in[24]; const float* bf3 = (const float*)d_in[25];
    const int*   ei    = (const int*)d_in[26];
    const int*   batch = (const int*)d_in[27];
    float* out = (float*)d_out;

    float *x16, *z1, *z2, *z3, *sum, *sq;
    cudaGetSymbolAddress((void**)&x16, g_x16);
    cudaGetSymbolAddress((void**)&z1,  g_z1);
    cudaGetSymbolAddress((void**)&z2,  g_z2);
    cudaGetSymbolAddress((void**)&z3,  g_z3);
    cudaGetSymbolAddress((void**)&sum, g_sum);
    cudaGetSymbolAddress((void**)&sq,  g_sq);

    const int T = 256;
    k_edge<<<(Ee + T - 1) / T, T>>>(ea, w_edge, b_edge, ei, x);
    k_scan<<<1, 1024>>>();
    k_scatter<<<(Ee + T - 1) / T, T>>>(ei);

    const int LGRID = Nn / 8;   // 1536 blocks * 4 warps * 2 rows = 12288
    k_layer<16, FIN, Hh><<<LGRID, 128>>>(x16, w1, b1, z1, sum, sq);
    k_norm<Hh><<<Nn * Hh / 4 / T, T>>>(z1, g1, be1, sum, sq);
    k_layer<Hh, Hh, H2><<<LGRID, 128>>>(z1, w2, b2, z2, sum + 64, sq + 64);
    k_norm<H2><<<Nn * H2 / 4 / T, T>>>(z2, g2, be2, sum + 64, sq + 64);
    k_layer<H2, H2, H2><<<LGRID, 128>>>(z2, w3, b3, z3, sum + 128, sq + 128);

    k_pool<<<96, T>>>(z3, batch, g3, be3);

    k_mlp1<<<8, T>>>(wf1, bf1, gf1, bef1, out);
    k_mlp2<<<8, T>>>(wf2, bf2, gf2, bef2);
    k_mlp3<<<5, T>>>(wf3, bf3, out);
}